// round 5
// baseline (speedup 1.0000x reference)
#include <cuda_runtime.h>

#define BB 16
#define TT 1024
#define SS 256
#define CC 256
#define LN_EPS 1e-3f

#define TTILE 16
#define TG 4

typedef unsigned long long ull;

// ---------------- scratch (device globals; no allocations) ----------------
__device__ float g_part[BB * 16 * SS * 16];  // conv partials: [b][chunk16][s][path*8+cc]
__device__ float g_cw[BB * SS * 16];
__device__ float g_ca[BB * SS * 16];

// ---------------- helpers ----------------
// sm_100a NOTE: tanh.approx.f32 is NOT a fast MUFU op on this chip (R4: +600us
// from software-emulated tanh). Keep silu on EX2 + RCP.
__device__ __forceinline__ float silu_f(float x) {
    float e = __expf(-x);
    return __fdividef(x, 1.0f + e);
}
__device__ __forceinline__ ull pk2(float lo, float hi) {
    ull r; asm("mov.b64 %0, {%1, %2};" : "=l"(r) : "f"(lo), "f"(hi)); return r;
}
__device__ __forceinline__ void upk2(ull v, float& lo, float& hi) {
    asm("mov.b64 {%0, %1}, %2;" : "=f"(lo), "=f"(hi) : "l"(v));
}
__device__ __forceinline__ ull ffma2(ull a, ull b, ull c) {
    ull d; asm("fma.rn.f32x2 %0, %1, %2, %3;" : "=l"(d) : "l"(a), "l"(b), "l"(c)); return d;
}

// ================= K1a: conv partials over 16-channel chunks =================
// grid = B*16 blocks, 256 threads (thread = s)
__global__ __launch_bounds__(256) void k1a_conv(
    const float* __restrict__ ctx,
    const float* __restrict__ wcw,
    const float* __restrict__ wca)
{
    __shared__ float s_ctx[SS * 17];
    __shared__ float s_w[2][3 * 16 * 8];

    int b = blockIdx.x >> 4;
    int chunk = blockIdx.x & 15;
    int c0 = chunk * 16;
    int tid = threadIdx.x;

    for (int i = tid; i < SS * 16; i += 256) {
        int row = i >> 4, c = i & 15;
        s_ctx[row * 17 + c] = ctx[((size_t)b * SS + row) * CC + c0 + c];
    }
    for (int i = tid; i < 3 * 16 * 8; i += 256) {
        int k = i / 128, rem = i % 128;   // rem = c*8+cc over the 16-chunk
        s_w[0][i] = wcw[(size_t)k * CC * 8 + (size_t)c0 * 8 + rem];
        s_w[1][i] = wca[(size_t)k * CC * 8 + (size_t)c0 * 8 + rem];
    }
    __syncthreads();

    int s = tid;
    float hw[8], ha[8];
    #pragma unroll
    for (int cc = 0; cc < 8; cc++) { hw[cc] = 0.f; ha[cc] = 0.f; }

    #pragma unroll
    for (int k = 0; k < 3; k++) {
        int row = s + k - 1;
        if (row < 0 || row >= SS) continue;
        for (int c = 0; c < 16; c++) {
            float v = s_ctx[row * 17 + c];
            #pragma unroll
            for (int cc = 0; cc < 8; cc++) {
                hw[cc] = fmaf(v, s_w[0][(k * 16 + c) * 8 + cc], hw[cc]);
                ha[cc] = fmaf(v, s_w[1][(k * 16 + c) * 8 + cc], ha[cc]);
            }
        }
    }
    float* dst = &g_part[(((size_t)b * 16 + chunk) * SS + s) * 16];
    #pragma unroll
    for (int cc = 0; cc < 8; cc++) { dst[cc] = hw[cc]; dst[8 + cc] = ha[cc]; }
}

// ========== K1b: cumsum + reduce partials + LN + silu + c-vectors ==========
// grid = B blocks, 256 threads (thread = s)
__global__ __launch_bounds__(256) void k1b_setup(
    const float* __restrict__ dur,
    const float* __restrict__ bcw, const float* __restrict__ glnw,
    const float* __restrict__ blnw, const float* __restrict__ w1w,
    const float* __restrict__ b1w,
    const float* __restrict__ bca, const float* __restrict__ glna,
    const float* __restrict__ blna, const float* __restrict__ w1a,
    const float* __restrict__ b1a)
{
    __shared__ float s_scan[SS];
    int b = blockIdx.x, s = threadIdx.x;

    float d = dur[(size_t)b * SS + s];
    s_scan[s] = d;
    __syncthreads();
    for (int off = 1; off < SS; off <<= 1) {
        float v = (s >= off) ? s_scan[s - off] : 0.f;
        __syncthreads();
        s_scan[s] += v;
        __syncthreads();
    }
    float e0 = s_scan[s];
    float s0 = e0 - d;

    float h[16];
    #pragma unroll
    for (int p = 0; p < 16; p++) h[p] = 0.f;
    for (int ch = 0; ch < 16; ch++) {
        const float* src = &g_part[(((size_t)b * 16 + ch) * SS + s) * 16];
        #pragma unroll
        for (int p = 0; p < 16; p++) h[p] += src[p];
    }

    for (int p = 0; p < 2; p++) {
        const float* bconv = (p == 0) ? bcw : bca;
        const float* gln   = (p == 0) ? glnw : glna;
        const float* bln   = (p == 0) ? blnw : blna;
        const float* w1    = (p == 0) ? w1w : w1a;
        const float* b1    = (p == 0) ? b1w : b1a;
        float* dst         = (p == 0) ? g_cw : g_ca;

        float hv[8];
        float mu = 0.f;
        #pragma unroll
        for (int cc = 0; cc < 8; cc++) {
            hv[cc] = h[p * 8 + cc] + bconv[cc];
            mu += hv[cc];
        }
        mu *= 0.125f;
        float var = 0.f;
        #pragma unroll
        for (int cc = 0; cc < 8; cc++) {
            float dd = hv[cc] - mu;
            var += dd * dd;
        }
        var *= 0.125f;
        float inv = rsqrtf(var + LN_EPS);
        float hs[8];
        #pragma unroll
        for (int cc = 0; cc < 8; cc++) {
            float xx = (hv[cc] - mu) * inv * gln[cc] + bln[cc];
            float e = __expf(-xx);
            hs[cc] = __fdividef(xx, 1.0f + e);
        }

        #pragma unroll
        for (int j = 0; j < 16; j++) {
            float val = b1[j] - s0 * w1[8 * 16 + j] + (e0 + s0) * w1[9 * 16 + j];
            #pragma unroll
            for (int cc = 0; cc < 8; cc++)
                val = fmaf(hs[cc], w1[cc * 16 + j], val);
            dst[((size_t)b * SS + s) * 16 + j] = val;
        }
    }
}

// ===================== K2: fused main kernel =====================
// grid = (T/TTILE, B), 256 threads
// smem floats:
//   s_cw    [0,      4352)  256*17    (aliased by s_concat later)
//   s_ca    [4352,   8704)  256*17    (tail aliased by s_concat later)
//   s_wt    [8704,  12800)  [t][256]
//   s_w2w   [12800, 13056)
//   s_w2a   [13056, 13312)
//   s_small [13312, 13408)
//   s_part  [13408, 15456)  16*8*16
//   s_concat = sm + 0, [t][276] = 4416 floats (alias, used after 1c)
#define K2_SMEM_FLOATS 15456
#define K2_SMEM_BYTES (K2_SMEM_FLOATS * 4)

__global__ __launch_bounds__(256, 2) void k2_main(
    const float* __restrict__ ctx, const float* __restrict__ mask,
    const float* __restrict__ w1w, const float* __restrict__ w2w,
    const float* __restrict__ b2w, const float* __restrict__ wpw,
    const float* __restrict__ bpw,
    const float* __restrict__ w1a, const float* __restrict__ w2a,
    const float* __restrict__ b2a,
    const float* __restrict__ wpa, const float* __restrict__ bpa,
    float* __restrict__ out)
{
    extern __shared__ float sm[];
    float* s_cw     = sm;
    float* s_ca     = sm + 4352;
    float* s_wt     = sm + 8704;
    float* s_w2w    = sm + 12800;
    float* s_w2a    = sm + 13056;
    float* s_small  = sm + 13312;
    float* s_part   = sm + 13408;
    float* s_concat = sm;           // alias; live only after phase 1c

    int tid = threadIdx.x;
    int lane = tid & 31, wid = tid >> 5;
    int b = blockIdx.y;
    int t0 = blockIdx.x * TTILE;

    // ---- load weights ----
    s_w2w[tid] = w2w[tid];
    s_w2a[tid] = w2a[tid];
    if (tid < 16) {
        s_small[tid]      = w1w[128 + tid] - w1w[144 + tid];  // dw
        s_small[16 + tid] = w1a[128 + tid] - w1a[144 + tid];  // da
        s_small[32 + tid] = wpw[tid];
        s_small[48 + tid] = b2w[tid];
        s_small[64 + tid] = b2a[tid];
    }
    {
        const float4* cw4 = (const float4*)&g_cw[((size_t)b * SS + tid) * 16];
        const float4* ca4 = (const float4*)&g_ca[((size_t)b * SS + tid) * 16];
        #pragma unroll
        for (int q = 0; q < 4; q++) {
            float4 v = cw4[q];
            s_cw[tid * 17 + q * 4 + 0] = v.x; s_cw[tid * 17 + q * 4 + 1] = v.y;
            s_cw[tid * 17 + q * 4 + 2] = v.z; s_cw[tid * 17 + q * 4 + 3] = v.w;
            float4 w = ca4[q];
            s_ca[tid * 17 + q * 4 + 0] = w.x; s_ca[tid * 17 + q * 4 + 1] = w.y;
            s_ca[tid * 17 + q * 4 + 2] = w.z; s_ca[tid * 17 + q * 4 + 3] = w.w;
        }
    }
    float bp0 = bpw[0];
    __syncthreads();

    // ---- Phase 1a: logits via layer-2 MLP (scalar FFMA) ----
    for (int g = 0; g < TTILE / TG; g++) {
        float y[TG][16];
        #pragma unroll
        for (int u = 0; u < TG; u++)
            #pragma unroll
            for (int i = 0; i < 16; i++) y[u][i] = s_small[48 + i];

        #pragma unroll
        for (int j = 0; j < 16; j++) {
            float cv = s_cw[tid * 17 + j];
            float dv = s_small[j];
            float xj[TG];
            #pragma unroll
            for (int u = 0; u < TG; u++)
                xj[u] = silu_f(fmaf((float)(t0 + g * TG + u), dv, cv));
            #pragma unroll
            for (int i = 0; i < 16; i++) {
                float w = s_w2w[j * 16 + i];
                #pragma unroll
                for (int u = 0; u < TG; u++)
                    y[u][i] = fmaf(xj[u], w, y[u][i]);
            }
        }
        #pragma unroll
        for (int u = 0; u < TG; u++) {
            float lg = bp0;
            #pragma unroll
            for (int i = 0; i < 16; i++)
                lg = fmaf(silu_f(y[u][i]), s_small[32 + i], lg);
            s_wt[(g * TG + u) * SS + tid] = lg;
        }
    }
    __syncthreads();

    // ---- Phase 1b: warp-private masked softmax (warp wid owns t = 2wid, 2wid+1) ----
    {
        const float* mask0 = mask + (size_t)b * TT * SS;
        #pragma unroll
        for (int tt = 0; tt < 2; tt++) {
            int t = wid * 2 + tt;
            float lg[8];
            #pragma unroll
            for (int k = 0; k < 8; k++) {
                int s = lane + 32 * k;
                float m0 = mask0[s];
                lg[k] = fmaf(m0, s_wt[t * SS + s], (1.0f - m0) * -1000000.0f);
            }
            float mx = lg[0];
            #pragma unroll
            for (int k = 1; k < 8; k++) mx = fmaxf(mx, lg[k]);
            #pragma unroll
            for (int off = 16; off > 0; off >>= 1)
                mx = fmaxf(mx, __shfl_xor_sync(0xffffffffu, mx, off));
            float p[8], sum = 0.f;
            #pragma unroll
            for (int k = 0; k < 8; k++) { p[k] = __expf(lg[k] - mx); sum += p[k]; }
            #pragma unroll
            for (int off = 16; off > 0; off >>= 1)
                sum += __shfl_xor_sync(0xffffffffu, sum, off);
            float inv = __fdividef(1.0f, sum);
            const float* mrow = mask + ((size_t)b * TT + t0 + t) * SS;
            float* orow = out + ((size_t)b * TT + t0 + t) * SS;
            #pragma unroll
            for (int k = 0; k < 8; k++) {
                int s = lane + 32 * k;
                float wv = p[k] * inv * mrow[s];
                s_wt[t * SS + s] = wv;
                orow[s] = wv;
            }
        }
    }
    __syncthreads();

    // ---- Phase 1c: a-path MLP, weight by wv, value-migrating butterfly over s ----
    for (int g = 0; g < TTILE / TG; g++) {
        float y[TG][16];
        #pragma unroll
        for (int u = 0; u < TG; u++)
            #pragma unroll
            for (int i = 0; i < 16; i++) y[u][i] = s_small[64 + i];

        #pragma unroll
        for (int j = 0; j < 16; j++) {
            float cv = s_ca[tid * 17 + j];
            float dv = s_small[16 + j];
            float xj[TG];
            #pragma unroll
            for (int u = 0; u < TG; u++)
                xj[u] = silu_f(fmaf((float)(t0 + g * TG + u), dv, cv));
            #pragma unroll
            for (int i = 0; i < 16; i++) {
                float w = s_w2a[j * 16 + i];
                #pragma unroll
                for (int u = 0; u < TG; u++)
                    y[u][i] = fmaf(xj[u], w, y[u][i]);
            }
        }
        #pragma unroll
        for (int u = 0; u < TG; u++) {
            int t = g * TG + u;
            float wv = s_wt[t * SS + tid];
            float v[16];
            #pragma unroll
            for (int i = 0; i < 16; i++)
                v[i] = silu_f(y[u][i]) * wv;
            // value-migrating butterfly: 16 values x 32 lanes -> lane pair (l, l^1)
            // ends holding the s-sum for m = (lane>>1)&15
            #pragma unroll
            for (int k = 0; k < 8; k++) {
                float sent = (lane & 16) ? v[k] : v[k + 8];
                float keep = (lane & 16) ? v[k + 8] : v[k];
                v[k] = keep + __shfl_xor_sync(0xffffffffu, sent, 16);
            }
            #pragma unroll
            for (int k = 0; k < 4; k++) {
                float sent = (lane & 8) ? v[k] : v[k + 4];
                float keep = (lane & 8) ? v[k + 4] : v[k];
                v[k] = keep + __shfl_xor_sync(0xffffffffu, sent, 8);
            }
            #pragma unroll
            for (int k = 0; k < 2; k++) {
                float sent = (lane & 4) ? v[k] : v[k + 2];
                float keep = (lane & 4) ? v[k + 2] : v[k];
                v[k] = keep + __shfl_xor_sync(0xffffffffu, sent, 4);
            }
            {
                float sent = (lane & 2) ? v[0] : v[1];
                float keep = (lane & 2) ? v[1] : v[0];
                v[0] = keep + __shfl_xor_sync(0xffffffffu, sent, 2);
            }
            v[0] += __shfl_xor_sync(0xffffffffu, v[0], 1);
            if ((lane & 1) == 0)
                s_part[(t * 8 + wid) * 16 + ((lane >> 1) & 15)] = v[0];
        }
    }
    __syncthreads();

    // ---- Phase 1d: finish aux reduction -> s_concat[t][256+m] ----
    {
        int t = tid >> 4, m = tid & 15;
        float a = 0.f;
        #pragma unroll
        for (int w8 = 0; w8 < 8; w8++)
            a += s_part[(t * 8 + w8) * 16 + m];
        s_concat[t * 276 + 256 + m] = a;
    }

    // ---- Phase 2: aligned = w @ context (scalar) ----
    int c64 = tid & 63;
    int tg = (tid >> 6) * 4;
    {
        float acc[4][4];
        #pragma unroll
        for (int u = 0; u < 4; u++)
            #pragma unroll
            for (int q = 0; q < 4; q++) acc[u][q] = 0.f;
        const float4* ctx4 = (const float4*)(ctx + (size_t)b * SS * CC);
        for (int s = 0; s < SS; s++) {
            float4 v = ctx4[s * 64 + c64];
            #pragma unroll
            for (int u = 0; u < 4; u++) {
                float wv = s_wt[(tg + u) * SS + s];
                acc[u][0] = fmaf(wv, v.x, acc[u][0]);
                acc[u][1] = fmaf(wv, v.y, acc[u][1]);
                acc[u][2] = fmaf(wv, v.z, acc[u][2]);
                acc[u][3] = fmaf(wv, v.w, acc[u][3]);
            }
        }
        #pragma unroll
        for (int u = 0; u < 4; u++) {
            float4 o = make_float4(acc[u][0], acc[u][1], acc[u][2], acc[u][3]);
            *(float4*)&s_concat[(tg + u) * 276 + c64 * 4] = o;
        }
    }
    __syncthreads();

    // ---- Phase 3: out_aligned = concat @ w_pa + b_pa  (f32x2 PROBE phase) ----
    {
        ull accp[4][4];
        #pragma unroll
        for (int u = 0; u < 4; u++)
            #pragma unroll
            for (int q = 0; q < 4; q++) accp[u][q] = 0ULL;
        const float4* wpa4 = (const float4*)wpa;
        for (int kp = 0; kp < 272 / 2; kp++) {
            int k = kp * 2;
            float4 wa = wpa4[k * 64 + c64];
            float4 wb = wpa4[(k + 1) * 64 + c64];
            ull wx = pk2(wa.x, wb.x), wy = pk2(wa.y, wb.y);
            ull wz = pk2(wa.z, wb.z), ww = pk2(wa.w, wb.w);
            #pragma unroll
            for (int u = 0; u < 4; u++) {
                ull xq = *(const ull*)&s_concat[(tg + u) * 276 + k];
                accp[u][0] = ffma2(xq, wx, accp[u][0]);
                accp[u][1] = ffma2(xq, wy, accp[u][1]);
                accp[u][2] = ffma2(xq, wz, accp[u][2]);
                accp[u][3] = ffma2(xq, ww, accp[u][3]);
            }
        }
        float4 bp = ((const float4*)bpa)[c64];
        float* oal = out + (size_t)BB * TT * SS;
        #pragma unroll
        for (int u = 0; u < 4; u++) {
            float l, h;
            float4 o;
            upk2(accp[u][0], l, h); o.x = bp.x + l + h;
            upk2(accp[u][1], l, h); o.y = bp.y + l + h;
            upk2(accp[u][2], l, h); o.z = bp.z + l + h;
            upk2(accp[u][3], l, h); o.w = bp.w + l + h;
            ((float4*)oal)[(((size_t)b * TT + (t0 + tg + u)) * CC + c64 * 4) >> 2] = o;
        }
    }
}

// ============================ launch ============================
extern "C" void kernel_launch(void* const* d_in, const int* in_sizes, int n_in,
                              void* d_out, int out_size) {
    (void)in_sizes; (void)n_in; (void)out_size;
    const float* ctx  = (const float*)d_in[0];
    const float* dur  = (const float*)d_in[1];
    const float* mask = (const float*)d_in[2];
    const float* wcw  = (const float*)d_in[3];
    const float* bcw  = (const float*)d_in[4];
    const float* glnw = (const float*)d_in[5];
    const float* blnw = (const float*)d_in[6];
    const float* w1w  = (const float*)d_in[7];
    const float* b1w  = (const float*)d_in[8];
    const float* w2w  = (const float*)d_in[9];
    const float* b2w  = (const float*)d_in[10];
    const float* wpw  = (const float*)d_in[11];
    const float* bpw  = (const float*)d_in[12];
    const float* wca  = (const float*)d_in[13];
    const float* bca  = (const float*)d_in[14];
    const float* glna = (const float*)d_in[15];
    const float* blna = (const float*)d_in[16];
    const float* w1a  = (const float*)d_in[17];
    const float* b1a  = (const float*)d_in[18];
    const float* w2a  = (const float*)d_in[19];
    const float* b2a  = (const float*)d_in[20];
    const float* wpa  = (const float*)d_in[21];
    const float* bpa  = (const float*)d_in[22];
    float* out = (float*)d_out;

    k1a_conv<<<BB * 16, 256>>>(ctx, wcw, wca);
    k1b_setup<<<BB, 256>>>(dur, bcw, glnw, blnw, w1w, b1w,
                           bca, glna, blna, w1a, b1a);

    cudaFuncSetAttribute(k2_main, cudaFuncAttributeMaxDynamicSharedMemorySize,
                         K2_SMEM_BYTES);
    dim3 grid(TT / TTILE, BB);
    k2_main<<<grid, 256, K2_SMEM_BYTES>>>(
        ctx, mask, w1w, w2w, b2w, wpw, bpw,
        w1a, w2a, b2a, wpa, bpa, out);
}

// round 6
// speedup vs baseline: 4.6866x; 4.6866x over previous
#include <cuda_runtime.h>

#define BB 16
#define TT 1024
#define SS 256
#define CC 256
#define LN_EPS 1e-3f

#define TTILE 16   // t's per block in k2
#define TG 4       // t-group for register blocking

// ---------------- scratch (device globals; no allocations) ----------------
__device__ float g_part[BB * 8 * SS * 16];  // conv partial sums: [b][chunk][s][path*8+cc]
__device__ float g_cw[BB * SS * 16];        // layer-1 constant vector, w path
__device__ float g_ca[BB * SS * 16];        // layer-1 constant vector, a path

// sm_100a lessons (measured):
//  - tanh.approx.f32 silu: +600us (R4). BANNED.
//  - fma.rn.f32x2 inline asm: +800us+ (R5). BANNED.
// Keep silu on EX2 + RCP.
__device__ __forceinline__ float silu_f(float x) {
    float e = __expf(-x);
    return __fdividef(x, 1.0f + e);
}

// ================= K1a: conv partials over 32-channel chunks =================
// grid = B*8 blocks, 256 threads (thread = s)   [R1-proven: 18.7us]
__global__ __launch_bounds__(256) void k1a_conv(
    const float* __restrict__ ctx,
    const float* __restrict__ wcw,
    const float* __restrict__ wca)
{
    __shared__ float s_ctx[SS * 33];
    __shared__ float s_w[2][3 * 32 * 8];

    int b = blockIdx.x >> 3;
    int chunk = blockIdx.x & 7;
    int c0 = chunk * 32;
    int tid = threadIdx.x;

    for (int i = tid; i < SS * 32; i += 256) {
        int row = i >> 5, c = i & 31;
        s_ctx[row * 33 + c] = ctx[((size_t)b * SS + row) * CC + c0 + c];
    }
    for (int i = tid; i < 3 * 32 * 8; i += 256) {
        int k = i / 256, rem = i % 256;   // rem = c*8+cc over the 32-chunk
        s_w[0][i] = wcw[(size_t)k * CC * 8 + (size_t)c0 * 8 + rem];
        s_w[1][i] = wca[(size_t)k * CC * 8 + (size_t)c0 * 8 + rem];
    }
    __syncthreads();

    int s = tid;
    float hw[8], ha[8];
    #pragma unroll
    for (int cc = 0; cc < 8; cc++) { hw[cc] = 0.f; ha[cc] = 0.f; }

    #pragma unroll
    for (int k = 0; k < 3; k++) {
        int row = s + k - 1;
        if (row < 0 || row >= SS) continue;
        for (int c = 0; c < 32; c++) {
            float v = s_ctx[row * 33 + c];
            #pragma unroll
            for (int cc = 0; cc < 8; cc++) {
                hw[cc] = fmaf(v, s_w[0][(k * 32 + c) * 8 + cc], hw[cc]);
                ha[cc] = fmaf(v, s_w[1][(k * 32 + c) * 8 + cc], ha[cc]);
            }
        }
    }
    float* dst = &g_part[(((size_t)b * 8 + chunk) * SS + s) * 16];
    #pragma unroll
    for (int cc = 0; cc < 8; cc++) { dst[cc] = hw[cc]; dst[8 + cc] = ha[cc]; }
}

// ========== K1b: cumsum + reduce partials + LN + silu + c-vectors ==========
// grid = B blocks, 256 threads (thread = s)
__global__ __launch_bounds__(256) void k1b_setup(
    const float* __restrict__ dur,
    const float* __restrict__ bcw, const float* __restrict__ glnw,
    const float* __restrict__ blnw, const float* __restrict__ w1w,
    const float* __restrict__ b1w,
    const float* __restrict__ bca, const float* __restrict__ glna,
    const float* __restrict__ blna, const float* __restrict__ w1a,
    const float* __restrict__ b1a)
{
    __shared__ float s_scan[SS];
    int b = blockIdx.x, s = threadIdx.x;

    float d = dur[(size_t)b * SS + s];
    s_scan[s] = d;
    __syncthreads();
    for (int off = 1; off < SS; off <<= 1) {
        float v = (s >= off) ? s_scan[s - off] : 0.f;
        __syncthreads();
        s_scan[s] += v;
        __syncthreads();
    }
    float e0 = s_scan[s];
    float s0 = e0 - d;

    float h[16];
    #pragma unroll
    for (int p = 0; p < 16; p++) h[p] = 0.f;
    for (int ch = 0; ch < 8; ch++) {
        const float* src = &g_part[(((size_t)b * 8 + ch) * SS + s) * 16];
        #pragma unroll
        for (int p = 0; p < 16; p++) h[p] += src[p];
    }

    for (int p = 0; p < 2; p++) {
        const float* bconv = (p == 0) ? bcw : bca;
        const float* gln   = (p == 0) ? glnw : glna;
        const float* bln   = (p == 0) ? blnw : blna;
        const float* w1    = (p == 0) ? w1w : w1a;
        const float* b1    = (p == 0) ? b1w : b1a;
        float* dst         = (p == 0) ? g_cw : g_ca;

        float hv[8];
        float mu = 0.f;
        #pragma unroll
        for (int cc = 0; cc < 8; cc++) {
            hv[cc] = h[p * 8 + cc] + bconv[cc];
            mu += hv[cc];
        }
        mu *= 0.125f;
        float var = 0.f;
        #pragma unroll
        for (int cc = 0; cc < 8; cc++) {
            float dd = hv[cc] - mu;
            var += dd * dd;
        }
        var *= 0.125f;
        float inv = rsqrtf(var + LN_EPS);
        float hs[8];
        #pragma unroll
        for (int cc = 0; cc < 8; cc++)
            hs[cc] = silu_f((hv[cc] - mu) * inv * gln[cc] + bln[cc]);

        #pragma unroll
        for (int j = 0; j < 16; j++) {
            float val = b1[j] - s0 * w1[8 * 16 + j] + (e0 + s0) * w1[9 * 16 + j];
            #pragma unroll
            for (int cc = 0; cc < 8; cc++)
                val = fmaf(hs[cc], w1[cc * 16 + j], val);
            dst[((size_t)b * SS + s) * 16 + j] = val;
        }
    }
}

// ===================== K2: fused main kernel =====================
// grid = (T/TTILE, B), 256 threads   [R1 layout, stride-272 s_concat]
// dyn smem layout (floats):
//   s_cw    [0,      4352)  256*17   (aliased as s_concat 16*272 later)
//   s_ca    [4352,   8704)  256*17
//   s_wt    [8704,  12800)  16*256
//   s_w2w   [12800, 13056)
//   s_w2a   [13056, 13312)
//   s_small [13312, 13408)  dw16 | da16 | wpw16 | b2w16 | b2a16
//   s_part  [13408, 15456)  16*8*16
//   s_red   [15456, 15496)  (kept for layout identity; unused now)
#define K2_SMEM_FLOATS 15496
#define K2_SMEM_BYTES (K2_SMEM_FLOATS * 4)

__global__ __launch_bounds__(256, 2) void k2_main(
    const float* __restrict__ ctx, const float* __restrict__ mask,
    const float* __restrict__ w1w, const float* __restrict__ w2w,
    const float* __restrict__ b2w, const float* __restrict__ wpw,
    const float* __restrict__ bpw,
    const float* __restrict__ w1a, const float* __restrict__ w2a,
    const float* __restrict__ b2a,
    const float* __restrict__ wpa, const float* __restrict__ bpa,
    float* __restrict__ out)
{
    extern __shared__ float sm[];
    float* s_cw     = sm;
    float* s_ca     = sm + 4352;
    float* s_wt     = sm + 8704;
    float* s_w2w    = sm + 12800;
    float* s_w2a    = sm + 13056;
    float* s_small  = sm + 13312;
    float* s_part   = sm + 13408;
    float* s_concat = s_cw;  // alias: s_cw dead after phase 1a

    int tid = threadIdx.x;
    int lane = tid & 31, wid = tid >> 5;
    int b = blockIdx.y;
    int t0 = blockIdx.x * TTILE;

    // ---- load weights ----
    s_w2w[tid] = w2w[tid];
    s_w2a[tid] = w2a[tid];
    if (tid < 16) {
        s_small[tid]      = w1w[128 + tid] - w1w[144 + tid];  // dw
        s_small[16 + tid] = w1a[128 + tid] - w1a[144 + tid];  // da
        s_small[32 + tid] = wpw[tid];
        s_small[48 + tid] = b2w[tid];
        s_small[64 + tid] = b2a[tid];
    }
    {
        const float4* cw4 = (const float4*)&g_cw[((size_t)b * SS + tid) * 16];
        const float4* ca4 = (const float4*)&g_ca[((size_t)b * SS + tid) * 16];
        #pragma unroll
        for (int q = 0; q < 4; q++) {
            float4 v = cw4[q];
            s_cw[tid * 17 + q * 4 + 0] = v.x; s_cw[tid * 17 + q * 4 + 1] = v.y;
            s_cw[tid * 17 + q * 4 + 2] = v.z; s_cw[tid * 17 + q * 4 + 3] = v.w;
            float4 w = ca4[q];
            s_ca[tid * 17 + q * 4 + 0] = w.x; s_ca[tid * 17 + q * 4 + 1] = w.y;
            s_ca[tid * 17 + q * 4 + 2] = w.z; s_ca[tid * 17 + q * 4 + 3] = w.w;
        }
    }
    float bp0 = bpw[0];
    __syncthreads();

    // ---- Phase 1a: logits for all TTILE t's (t-grouped by TG) ----
    for (int g = 0; g < TTILE / TG; g++) {
        float y[TG][16];
        #pragma unroll
        for (int u = 0; u < TG; u++)
            #pragma unroll
            for (int i = 0; i < 16; i++) y[u][i] = s_small[48 + i];

        for (int j = 0; j < 16; j++) {
            float cv = s_cw[tid * 17 + j];
            float dv = s_small[j];
            float xj[TG];
            #pragma unroll
            for (int u = 0; u < TG; u++)
                xj[u] = silu_f(fmaf((float)(t0 + g * TG + u), dv, cv));
            #pragma unroll
            for (int i = 0; i < 16; i++) {
                float w = s_w2w[j * 16 + i];
                #pragma unroll
                for (int u = 0; u < TG; u++)
                    y[u][i] = fmaf(xj[u], w, y[u][i]);
            }
        }
        #pragma unroll
        for (int u = 0; u < TG; u++) {
            float lg = bp0;
            #pragma unroll
            for (int i = 0; i < 16; i++)
                lg = fmaf(silu_f(y[u][i]), s_small[32 + i], lg);
            s_wt[(g * TG + u) * SS + tid] = lg;
        }
    }
    __syncthreads();

    // ---- Phase 1b: warp-private masked softmax (warp wid owns t = 2wid, 2wid+1) ----
    // (THE single change vs the 446us R1 kernel: no block barriers / s_red trees here)
    {
        const float* mask0 = mask + (size_t)b * TT * SS;
        #pragma unroll
        for (int tt = 0; tt < 2; tt++) {
            int t = wid * 2 + tt;
            float lg[8];
            #pragma unroll
            for (int k = 0; k < 8; k++) {
                int s = lane + 32 * k;
                float m0 = mask0[s];
                lg[k] = fmaf(m0, s_wt[t * SS + s], (1.0f - m0) * -1000000.0f);
            }
            float mx = lg[0];
            #pragma unroll
            for (int k = 1; k < 8; k++) mx = fmaxf(mx, lg[k]);
            #pragma unroll
            for (int off = 16; off > 0; off >>= 1)
                mx = fmaxf(mx, __shfl_xor_sync(0xffffffffu, mx, off));
            float p[8], sum = 0.f;
            #pragma unroll
            for (int k = 0; k < 8; k++) { p[k] = __expf(lg[k] - mx); sum += p[k]; }
            #pragma unroll
            for (int off = 16; off > 0; off >>= 1)
                sum += __shfl_xor_sync(0xffffffffu, sum, off);
            float inv = __fdividef(1.0f, sum);
            const float* mrow = mask + ((size_t)b * TT + t0 + t) * SS;
            float* orow = out + ((size_t)b * TT + t0 + t) * SS;
            #pragma unroll
            for (int k = 0; k < 8; k++) {
                int s = lane + 32 * k;
                float wv = p[k] * inv * mrow[s];
                s_wt[t * SS + s] = wv;
                orow[s] = wv;
            }
        }
    }
    __syncthreads();

    // ---- Phase 1c: a-path MLP, weighted + warp-reduced (R1 simple butterfly) ----
    for (int g = 0; g < TTILE / TG; g++) {
        float y[TG][16];
        #pragma unroll
        for (int u = 0; u < TG; u++)
            #pragma unroll
            for (int i = 0; i < 16; i++) y[u][i] = s_small[64 + i];

        for (int j = 0; j < 16; j++) {
            float cv = s_ca[tid * 17 + j];
            float dv = s_small[16 + j];
            float xj[TG];
            #pragma unroll
            for (int u = 0; u < TG; u++)
                xj[u] = silu_f(fmaf((float)(t0 + g * TG + u), dv, cv));
            #pragma unroll
            for (int i = 0; i < 16; i++) {
                float w = s_w2a[j * 16 + i];
                #pragma unroll
                for (int u = 0; u < TG; u++)
                    y[u][i] = fmaf(xj[u], w, y[u][i]);
            }
        }
        #pragma unroll
        for (int u = 0; u < TG; u++) {
            float wv = s_wt[(g * TG + u) * SS + tid];
            #pragma unroll
            for (int i = 0; i < 16; i++)
                y[u][i] = silu_f(y[u][i]) * wv;
        }
        #pragma unroll
        for (int off = 16; off > 0; off >>= 1)
            #pragma unroll
            for (int u = 0; u < TG; u++)
                #pragma unroll
                for (int i = 0; i < 16; i++)
                    y[u][i] += __shfl_xor_sync(0xffffffffu, y[u][i], off);
        if (lane == 0) {
            #pragma unroll
            for (int u = 0; u < TG; u++)
                #pragma unroll
                for (int i = 0; i < 16; i++)
                    s_part[((g * TG + u) * 8 + wid) * 16 + i] = y[u][i];
        }
    }
    __syncthreads();

    // ---- Phase 1d: finish aux reduction -> s_concat[t][256+m] ----
    {
        int t = tid >> 4, m = tid & 15;
        float a = 0.f;
        #pragma unroll
        for (int w8 = 0; w8 < 8; w8++)
            a += s_part[(t * 8 + w8) * 16 + m];
        s_concat[t * 272 + 256 + m] = a;
    }

    // ---- Phase 2: aligned = w @ context -> s_concat[t][0..255] ----
    int cg = (tid & 63) * 4;
    int tg = (tid >> 6) * 4;
    {
        float acc[4][4];
        #pragma unroll
        for (int u = 0; u < 4; u++)
            #pragma unroll
            for (int q = 0; q < 4; q++) acc[u][q] = 0.f;
        const float4* ctx4 = (const float4*)(ctx + (size_t)b * SS * CC);
        for (int s = 0; s < SS; s++) {
            float4 v = ctx4[s * 64 + (tid & 63)];
            #pragma unroll
            for (int u = 0; u < 4; u++) {
                float wv = s_wt[(tg + u) * SS + s];
                acc[u][0] = fmaf(wv, v.x, acc[u][0]);
                acc[u][1] = fmaf(wv, v.y, acc[u][1]);
                acc[u][2] = fmaf(wv, v.z, acc[u][2]);
                acc[u][3] = fmaf(wv, v.w, acc[u][3]);
            }
        }
        #pragma unroll
        for (int u = 0; u < 4; u++)
            #pragma unroll
            for (int q = 0; q < 4; q++)
                s_concat[(tg + u) * 272 + cg + q] = acc[u][q];
    }
    __syncthreads();

    // ---- Phase 3: out_aligned = concat @ w_pa + b_pa ----
    {
        float acc2[4][4];
        float4 bp = ((const float4*)bpa)[tid & 63];
        #pragma unroll
        for (int u = 0; u < 4; u++) {
            acc2[u][0] = bp.x; acc2[u][1] = bp.y;
            acc2[u][2] = bp.z; acc2[u][3] = bp.w;
        }
        const float4* wpa4 = (const float4*)wpa;
        for (int k = 0; k < 272; k++) {
            float4 wv = wpa4[k * 64 + (tid & 63)];
            #pragma unroll
            for (int u = 0; u < 4; u++) {
                float xv = s_concat[(tg + u) * 272 + k];
                acc2[u][0] = fmaf(xv, wv.x, acc2[u][0]);
                acc2[u][1] = fmaf(xv, wv.y, acc2[u][1]);
                acc2[u][2] = fmaf(xv, wv.z, acc2[u][2]);
                acc2[u][3] = fmaf(xv, wv.w, acc2[u][3]);
            }
        }
        float* oal = out + (size_t)BB * TT * SS;
        #pragma unroll
        for (int u = 0; u < 4; u++) {
            float4 o = make_float4(acc2[u][0], acc2[u][1], acc2[u][2], acc2[u][3]);
            ((float4*)oal)[(((size_t)b * TT + (t0 + tg + u)) * CC + cg) >> 2] = o;
        }
    }
}

// ============================ launch ============================
extern "C" void kernel_launch(void* const* d_in, const int* in_sizes, int n_in,
                              void* d_out, int out_size) {
    (void)in_sizes; (void)n_in; (void)out_size;
    const float* ctx  = (const float*)d_in[0];
    const float* dur  = (const float*)d_in[1];
    const float* mask = (const float*)d_in[2];
    const float* wcw  = (const float*)d_in[3];
    const float* bcw  = (const float*)d_in[4];
    const float* glnw = (const float*)d_in[5];
    const float* blnw = (const float*)d_in[6];
    const float* w1w  = (const float*)d_in[7];
    const float* b1w  = (const float*)d_in[8];
    const float* w2w  = (const float*)d_in[9];
    const float* b2w  = (const float*)d_in[10];
    const float* wpw  = (const float*)d_in[11];
    const float* bpw  = (const float*)d_in[12];
    const float* wca  = (const float*)d_in[13];
    const float* bca  = (const float*)d_in[14];
    const float* glna = (const float*)d_in[15];
    const float* blna = (const float*)d_in[16];
    const float* w1a  = (const float*)d_in[17];
    const float* b1a  = (const float*)d_in[18];
    const float* w2a  = (const float*)d_in[19];
    const float* b2a  = (const float*)d_in[20];
    const float* wpa  = (const float*)d_in[21];
    const float* bpa  = (const float*)d_in[22];
    float* out = (float*)d_out;

    k1a_conv<<<BB * 8, 256>>>(ctx, wcw, wca);
    k1b_setup<<<BB, 256>>>(dur, bcw, glnw, blnw, w1w, b1w,
                           bca, glna, blna, w1a, b1a);

    cudaFuncSetAttribute(k2_main, cudaFuncAttributeMaxDynamicSharedMemorySize,
                         K2_SMEM_BYTES);
    dim3 grid(TT / TTILE, BB);
    k2_main<<<grid, 256, K2_SMEM_BYTES>>>(
        ctx, mask, w1w, w2w, b2w, wpw, bpw,
        w1a, w2a, b2a, wpa, bpa, out);
}

// round 8
// speedup vs baseline: 5.0841x; 1.0848x over previous
#include <cuda_runtime.h>
#include <cstdint>

#define BB 16
#define TT 1024
#define SS 256
#define CC 256
#define LN_EPS 1e-3f

#define TTILE 16   // t's per block in k2
#define TG 4       // t-group for register blocking

// ---------------- scratch (device globals; no allocations) ----------------
__device__ float g_part[BB * 8 * SS * 16];  // conv partial sums
__device__ float g_cw[BB * SS * 16];        // layer-1 constant vector, w path
__device__ float g_ca[BB * SS * 16];        // layer-1 constant vector, a path

// sm_100a lessons (measured):
//  - tanh.approx.f32 silu: +600us (R4, sw-emulated). BANNED.
//  - fma.rn.f32x2 inline asm: catastrophic slowdown (R5). BANNED.
__device__ __forceinline__ float silu_f(float x) {
    float e = __expf(-x);
    return __fdividef(x, 1.0f + e);
}

// ---- TF32 helpers (3xTF32 split for fp32-grade tensor-core GEMM) ----
__device__ __forceinline__ uint32_t tf32_of(float x) {
    uint32_t r; asm("cvt.rna.tf32.f32 %0, %1;" : "=r"(r) : "f"(x)); return r;
}
__device__ __forceinline__ void tf32_split(float x, uint32_t& hi, uint32_t& lo) {
    hi = tf32_of(x);
    lo = tf32_of(x - __uint_as_float(hi));
}
__device__ __forceinline__ void mma_tf32(
    float& d0, float& d1, float& d2, float& d3,
    uint32_t a0, uint32_t a1, uint32_t a2, uint32_t a3,
    uint32_t b0, uint32_t b1)
{
    asm volatile(
        "mma.sync.aligned.m16n8k8.row.col.f32.tf32.tf32.f32 "
        "{%0,%1,%2,%3}, {%4,%5,%6,%7}, {%8,%9}, {%0,%1,%2,%3};"
        : "+f"(d0), "+f"(d1), "+f"(d2), "+f"(d3)
        : "r"(a0), "r"(a1), "r"(a2), "r"(a3), "r"(b0), "r"(b1));
}

// ================= K1a: conv partials over 32-channel chunks =================
__global__ __launch_bounds__(256) void k1a_conv(
    const float* __restrict__ ctx,
    const float* __restrict__ wcw,
    const float* __restrict__ wca)
{
    __shared__ float s_ctx[SS * 33];
    __shared__ float s_w[2][3 * 32 * 8];

    int b = blockIdx.x >> 3;
    int chunk = blockIdx.x & 7;
    int c0 = chunk * 32;
    int tid = threadIdx.x;

    for (int i = tid; i < SS * 32; i += 256) {
        int row = i >> 5, c = i & 31;
        s_ctx[row * 33 + c] = ctx[((size_t)b * SS + row) * CC + c0 + c];
    }
    for (int i = tid; i < 3 * 32 * 8; i += 256) {
        int k = i / 256, rem = i % 256;
        s_w[0][i] = wcw[(size_t)k * CC * 8 + (size_t)c0 * 8 + rem];
        s_w[1][i] = wca[(size_t)k * CC * 8 + (size_t)c0 * 8 + rem];
    }
    __syncthreads();

    int s = tid;
    float hw[8], ha[8];
    #pragma unroll
    for (int cc = 0; cc < 8; cc++) { hw[cc] = 0.f; ha[cc] = 0.f; }

    #pragma unroll
    for (int k = 0; k < 3; k++) {
        int row = s + k - 1;
        if (row < 0 || row >= SS) continue;
        for (int c = 0; c < 32; c++) {
            float v = s_ctx[row * 33 + c];
            #pragma unroll
            for (int cc = 0; cc < 8; cc++) {
                hw[cc] = fmaf(v, s_w[0][(k * 32 + c) * 8 + cc], hw[cc]);
                ha[cc] = fmaf(v, s_w[1][(k * 32 + c) * 8 + cc], ha[cc]);
            }
        }
    }
    float* dst = &g_part[(((size_t)b * 8 + chunk) * SS + s) * 16];
    #pragma unroll
    for (int cc = 0; cc < 8; cc++) { dst[cc] = hw[cc]; dst[8 + cc] = ha[cc]; }
}

// ========== K1b: cumsum + reduce partials + LN + silu + c-vectors ==========
__global__ __launch_bounds__(256) void k1b_setup(
    const float* __restrict__ dur,
    const float* __restrict__ bcw, const float* __restrict__ glnw,
    const float* __restrict__ blnw, const float* __restrict__ w1w,
    const float* __restrict__ b1w,
    const float* __restrict__ bca, const float* __restrict__ glna,
    const float* __restrict__ blna, const float* __restrict__ w1a,
    const float* __restrict__ b1a)
{
    __shared__ float s_scan[SS];
    int b = blockIdx.x, s = threadIdx.x;

    float d = dur[(size_t)b * SS + s];
    s_scan[s] = d;
    __syncthreads();
    for (int off = 1; off < SS; off <<= 1) {
        float v = (s >= off) ? s_scan[s - off] : 0.f;
        __syncthreads();
        s_scan[s] += v;
        __syncthreads();
    }
    float e0 = s_scan[s];
    float s0 = e0 - d;

    float h[16];
    #pragma unroll
    for (int p = 0; p < 16; p++) h[p] = 0.f;
    for (int ch = 0; ch < 8; ch++) {
        const float* src = &g_part[(((size_t)b * 8 + ch) * SS + s) * 16];
        #pragma unroll
        for (int p = 0; p < 16; p++) h[p] += src[p];
    }

    for (int p = 0; p < 2; p++) {
        const float* bconv = (p == 0) ? bcw : bca;
        const float* gln   = (p == 0) ? glnw : glna;
        const float* bln   = (p == 0) ? blnw : blna;
        const float* w1    = (p == 0) ? w1w : w1a;
        const float* b1    = (p == 0) ? b1w : b1a;
        float* dst         = (p == 0) ? g_cw : g_ca;

        float hv[8];
        float mu = 0.f;
        #pragma unroll
        for (int cc = 0; cc < 8; cc++) {
            hv[cc] = h[p * 8 + cc] + bconv[cc];
            mu += hv[cc];
        }
        mu *= 0.125f;
        float var = 0.f;
        #pragma unroll
        for (int cc = 0; cc < 8; cc++) {
            float dd = hv[cc] - mu;
            var += dd * dd;
        }
        var *= 0.125f;
        float inv = rsqrtf(var + LN_EPS);
        float hs[8];
        #pragma unroll
        for (int cc = 0; cc < 8; cc++)
            hs[cc] = silu_f((hv[cc] - mu) * inv * gln[cc] + bln[cc]);

        #pragma unroll
        for (int j = 0; j < 16; j++) {
            float val = b1[j] - s0 * w1[8 * 16 + j] + (e0 + s0) * w1[9 * 16 + j];
            #pragma unroll
            for (int cc = 0; cc < 8; cc++)
                val = fmaf(hs[cc], w1[cc * 16 + j], val);
            dst[((size_t)b * SS + s) * 16 + j] = val;
        }
    }
}

// ===================== K2: fused main kernel =====================
// grid = (T/TTILE, B), 256 threads
// smem floats:
//   s_cw     [0,     4352)  256*17  (aliased by s_concat, stride 276 -> 4416 spills into s_ca, safe after 1c)
//   s_ca     [4352,  8704)  256*17
//   s_wt     [8704, 12800)  [t][256]
//   s_w2w    [12800,13056)
//   s_w2a    [13056,13312)
//   s_small  [13312,13408)
//   s_part   [13408,15456)  16*8*16
//   s_wtF_hi [15456,19552)  tf32 A-fragment copy of w (hi), [ks][lane][reg]
//   s_wtF_lo [19552,23648)  tf32 A-fragment copy of w (lo)
#define K2_SMEM_FLOATS 23648
#define K2_SMEM_BYTES (K2_SMEM_FLOATS * 4)

__global__ __launch_bounds__(256, 2) void k2_main(
    const float* __restrict__ ctx, const float* __restrict__ mask,
    const float* __restrict__ w1w, const float* __restrict__ w2w,
    const float* __restrict__ b2w, const float* __restrict__ wpw,
    const float* __restrict__ bpw,
    const float* __restrict__ w1a, const float* __restrict__ w2a,
    const float* __restrict__ b2a,
    const float* __restrict__ wpa, const float* __restrict__ bpa,
    float* __restrict__ out)
{
    extern __shared__ float sm[];
    float* s_cw     = sm;
    float* s_ca     = sm + 4352;
    float* s_wt     = sm + 8704;
    float* s_w2w    = sm + 12800;
    float* s_w2a    = sm + 13056;
    float* s_small  = sm + 13312;
    float* s_part   = sm + 13408;
    uint32_t* u_wtF_hi = (uint32_t*)(sm + 15456);
    uint32_t* u_wtF_lo = (uint32_t*)(sm + 19552);
    float* s_concat = s_cw;  // alias; live only after phase 1c (stride 276)

    int tid = threadIdx.x;
    int lane = tid & 31, wid = tid >> 5;
    int b = blockIdx.y;
    int t0 = blockIdx.x * TTILE;

    // ---- load weights ----
    s_w2w[tid] = w2w[tid];
    s_w2a[tid] = w2a[tid];
    if (tid < 16) {
        s_small[tid]      = w1w[128 + tid] - w1w[144 + tid];  // dw
        s_small[16 + tid] = w1a[128 + tid] - w1a[144 + tid];  // da
        s_small[32 + tid] = wpw[tid];
        s_small[48 + tid] = b2w[tid];
        s_small[64 + tid] = b2a[tid];
    }
    {
        const float4* cw4 = (const float4*)&g_cw[((size_t)b * SS + tid) * 16];
        const float4* ca4 = (const float4*)&g_ca[((size_t)b * SS + tid) * 16];
        #pragma unroll
        for (int q = 0; q < 4; q++) {
            float4 v = cw4[q];
            s_cw[tid * 17 + q * 4 + 0] = v.x; s_cw[tid * 17 + q * 4 + 1] = v.y;
            s_cw[tid * 17 + q * 4 + 2] = v.z; s_cw[tid * 17 + q * 4 + 3] = v.w;
            float4 w = ca4[q];
            s_ca[tid * 17 + q * 4 + 0] = w.x; s_ca[tid * 17 + q * 4 + 1] = w.y;
            s_ca[tid * 17 + q * 4 + 2] = w.z; s_ca[tid * 17 + q * 4 + 3] = w.w;
        }
    }
    float bp0 = bpw[0];
    __syncthreads();

    // ---- Phase 1a: logits for all TTILE t's ----
    for (int g = 0; g < TTILE / TG; g++) {
        float y[TG][16];
        #pragma unroll
        for (int u = 0; u < TG; u++)
            #pragma unroll
            for (int i = 0; i < 16; i++) y[u][i] = s_small[48 + i];

        for (int j = 0; j < 16; j++) {
            float cv = s_cw[tid * 17 + j];
            float dv = s_small[j];
            float xj[TG];
            #pragma unroll
            for (int u = 0; u < TG; u++)
                xj[u] = silu_f(fmaf((float)(t0 + g * TG + u), dv, cv));
            #pragma unroll
            for (int i = 0; i < 16; i++) {
                float w = s_w2w[j * 16 + i];
                #pragma unroll
                for (int u = 0; u < TG; u++)
                    y[u][i] = fmaf(xj[u], w, y[u][i]);
            }
        }
        #pragma unroll
        for (int u = 0; u < TG; u++) {
            float lg = bp0;
            #pragma unroll
            for (int i = 0; i < 16; i++)
                lg = fmaf(silu_f(y[u][i]), s_small[32 + i], lg);
            s_wt[(g * TG + u) * SS + tid] = lg;
        }
    }
    __syncthreads();

    // ---- Phase 1b: warp-private masked softmax; also emit tf32 A-fragments ----
    {
        const float* mask0 = mask + (size_t)b * TT * SS;
        #pragma unroll
        for (int tt = 0; tt < 2; tt++) {
            int t = wid * 2 + tt;
            float lg[8];
            #pragma unroll
            for (int k = 0; k < 8; k++) {
                int s = lane + 32 * k;
                float m0 = mask0[s];
                lg[k] = fmaf(m0, s_wt[t * SS + s], (1.0f - m0) * -1000000.0f);
            }
            float mx = lg[0];
            #pragma unroll
            for (int k = 1; k < 8; k++) mx = fmaxf(mx, lg[k]);
            #pragma unroll
            for (int off = 16; off > 0; off >>= 1)
                mx = fmaxf(mx, __shfl_xor_sync(0xffffffffu, mx, off));
            float p[8], sum = 0.f;
            #pragma unroll
            for (int k = 0; k < 8; k++) { p[k] = __expf(lg[k] - mx); sum += p[k]; }
            #pragma unroll
            for (int off = 16; off > 0; off >>= 1)
                sum += __shfl_xor_sync(0xffffffffu, sum, off);
            float inv = __fdividef(1.0f, sum);
            const float* mrow = mask + ((size_t)b * TT + t0 + t) * SS;
            float* orow = out + ((size_t)b * TT + t0 + t) * SS;
            #pragma unroll
            for (int k = 0; k < 8; k++) {
                int s = lane + 32 * k;
                float wv = p[k] * inv * mrow[s];
                s_wt[t * SS + s] = wv;
                orow[s] = wv;
                // frag-layout tf32 split copy (A operand for phase-2 mma)
                uint32_t hi, lo;
                tf32_split(wv, hi, lo);
                int ks = s >> 3;
                int lf = ((t & 7) << 2) | (s & 3);
                int rg = (t >> 3) | (((s >> 2) & 1) << 1);
                int fi = ks * 128 + lf * 4 + rg;
                u_wtF_hi[fi] = hi;
                u_wtF_lo[fi] = lo;
            }
        }
    }
    __syncthreads();

    // ---- Phase 1c: a-path MLP, weighted + warp-reduced ----
    for (int g = 0; g < TTILE / TG; g++) {
        float y[TG][16];
        #pragma unroll
        for (int u = 0; u < TG; u++)
            #pragma unroll
            for (int i = 0; i < 16; i++) y[u][i] = s_small[64 + i];

        for (int j = 0; j < 16; j++) {
            float cv = s_ca[tid * 17 + j];
            float dv = s_small[16 + j];
            float xj[TG];
            #pragma unroll
            for (int u = 0; u < TG; u++)
                xj[u] = silu_f(fmaf((float)(t0 + g * TG + u), dv, cv));
            #pragma unroll
            for (int i = 0; i < 16; i++) {
                float w = s_w2a[j * 16 + i];
                #pragma unroll
                for (int u = 0; u < TG; u++)
                    y[u][i] = fmaf(xj[u], w, y[u][i]);
            }
        }
        #pragma unroll
        for (int u = 0; u < TG; u++) {
            float wv = s_wt[(g * TG + u) * SS + tid];
            #pragma unroll
            for (int i = 0; i < 16; i++)
                y[u][i] = silu_f(y[u][i]) * wv;
        }
        #pragma unroll
        for (int off = 16; off > 0; off >>= 1)
            #pragma unroll
            for (int u = 0; u < TG; u++)
                #pragma unroll
                for (int i = 0; i < 16; i++)
                    y[u][i] += __shfl_xor_sync(0xffffffffu, y[u][i], off);
        if (lane == 0) {
            #pragma unroll
            for (int u = 0; u < TG; u++)
                #pragma unroll
                for (int i = 0; i < 16; i++)
                    s_part[((g * TG + u) * 8 + wid) * 16 + i] = y[u][i];
        }
    }
    __syncthreads();

    // ---- Phase 1d: finish aux reduction -> s_concat[t][256+m] (stride 276) ----
    {
        int t = tid >> 4, m = tid & 15;
        float a = 0.f;
        #pragma unroll
        for (int w8 = 0; w8 < 8; w8++)
            a += s_part[(t * 8 + w8) * 16 + m];
        s_concat[t * 276 + 256 + m] = a;
    }

    // ---- Phase 2 (TENSOR CORES, 3xTF32): aligned = w @ ctx -> s_concat ----
    {
        int n_base = wid * 32;
        float acc[4][4];
        #pragma unroll
        for (int nt = 0; nt < 4; nt++)
            #pragma unroll
            for (int q = 0; q < 4; q++) acc[nt][q] = 0.f;

        const float* bp0p = ctx + (size_t)b * SS * CC + (lane & 3) * CC + (lane >> 2);
        #pragma unroll 4
        for (int ks = 0; ks < 32; ks++) {
            uint4 ah = *(const uint4*)&u_wtF_hi[ks * 128 + lane * 4];
            uint4 al = *(const uint4*)&u_wtF_lo[ks * 128 + lane * 4];
            const float* bk = bp0p + ks * 8 * CC;
            #pragma unroll
            for (int nt = 0; nt < 4; nt++) {
                int n0 = n_base + nt * 8;
                float bx0 = bk[n0];
                float bx1 = bk[4 * CC + n0];
                uint32_t bh0, bl0, bh1, bl1;
                tf32_split(bx0, bh0, bl0);
                tf32_split(bx1, bh1, bl1);
                mma_tf32(acc[nt][0], acc[nt][1], acc[nt][2], acc[nt][3],
                         ah.x, ah.y, ah.z, ah.w, bh0, bh1);
                mma_tf32(acc[nt][0], acc[nt][1], acc[nt][2], acc[nt][3],
                         ah.x, ah.y, ah.z, ah.w, bl0, bl1);
                mma_tf32(acc[nt][0], acc[nt][1], acc[nt][2], acc[nt][3],
                         al.x, al.y, al.z, al.w, bh0, bh1);
            }
        }
        int r0 = lane >> 2, c2 = 2 * (lane & 3);
        #pragma unroll
        for (int nt = 0; nt < 4; nt++) {
            int c = n_base + nt * 8 + c2;
            *(float2*)&s_concat[r0 * 276 + c]       = make_float2(acc[nt][0], acc[nt][1]);
            *(float2*)&s_concat[(r0 + 8) * 276 + c] = make_float2(acc[nt][2], acc[nt][3]);
        }
    }
    __syncthreads();

    // ---- Phase 3 (TENSOR CORES, 3xTF32): out_aligned = concat @ w_pa + b_pa ----
    {
        int n_base = wid * 32;
        float acc[4][4];
        #pragma unroll
        for (int nt = 0; nt < 4; nt++)
            #pragma unroll
            for (int q = 0; q < 4; q++) acc[nt][q] = 0.f;

        const float* aA = s_concat + (lane >> 2) * 276 + (lane & 3);
        const float* wp0 = wpa + (lane & 3) * CC + (lane >> 2);
        #pragma unroll 2
        for (int ks = 0; ks < 34; ks++) {
            float a0f = aA[ks * 8];
            float a1f = aA[8 * 276 + ks * 8];
            float a2f = aA[ks * 8 + 4];
            float a3f = aA[8 * 276 + ks * 8 + 4];
            uint32_t ah0, al0, ah1, al1, ah2, al2, ah3, al3;
            tf32_split(a0f, ah0, al0);
            tf32_split(a1f, ah1, al1);
            tf32_split(a2f, ah2, al2);
            tf32_split(a3f, ah3, al3);
            const float* wk = wp0 + ks * 8 * CC;
            #pragma unroll
            for (int nt = 0; nt < 4; nt++) {
                int n0 = n_base + nt * 8;
                float bx0 = wk[n0];
                float bx1 = wk[4 * CC + n0];
                uint32_t bh0, bl0, bh1, bl1;
                tf32_split(bx0, bh0, bl0);
                tf32_split(bx1, bh1, bl1);
                mma_tf32(acc[nt][0], acc[nt][1], acc[nt][2], acc[nt][3],
                         ah0, ah1, ah2, ah3, bh0, bh1);
                mma_tf32(acc[nt][0], acc[nt][1], acc[nt][2], acc[nt][3],
                         ah0, ah1, ah2, ah3, bl0, bl1);
                mma_tf32(acc[nt][0], acc[nt][1], acc[nt][2], acc[nt][3],
                         al0, al1, al2, al3, bh0, bh1);
            }
        }
        int r0 = lane >> 2, c2 = 2 * (lane & 3);
        float* oal = out + (size_t)BB * TT * SS;
        #pragma unroll
        for (int nt = 0; nt < 4; nt++) {
            int c = n_base + nt * 8 + c2;
            float2 bias = *(const float2*)&bpa[c];
            size_t o0 = ((size_t)b * TT + t0 + r0) * CC + c;
            size_t o1 = ((size_t)b * TT + t0 + r0 + 8) * CC + c;
            *(float2*)&oal[o0] = make_float2(acc[nt][0] + bias.x, acc[nt][1] + bias.y);
            *(float2*)&oal[o1] = make_float2(acc[nt][2] + bias.x, acc[nt][3] + bias.y);
        }
    }
}

// ============================ launch ============================
extern "C" void kernel_launch(void* const* d_in, const int* in_sizes, int n_in,
                              void* d_out, int out_size) {
    (void)in_sizes; (void)n_in; (void)out_size;
    const float* ctx  = (const float*)d_in[0];
    const float* dur  = (const float*)d_in[1];
    const float* mask = (const float*)d_in[2];
    const float* wcw  = (const float*)d_in[3];
    const float* bcw  = (const float*)d_in[4];
    const float* glnw = (const float*)d_in[5];
    const float* blnw = (const float*)d_in[6];
    const float* w1w  = (const float*)d_in[7];
    const float* b1w  = (const float*)d_in[8];
    const float* w2w  = (const float*)d_in[9];
    const float* b2w  = (const float*)d_in[10];
    const float* wpw  = (const float*)d_in[11];
    const float* bpw  = (const float*)d_in[12];
    const float* wca  = (const float*)d_in[13];
    const float* bca  = (const float*)d_in[14];
    const float* glna = (const float*)d_in[15];
    const float* blna = (const float*)d_in[16];
    const float* w1a  = (const float*)d_in[17];
    const float* b1a  = (const float*)d_in[18];
    const float* w2a  = (const float*)d_in[19];
    const float* b2a  = (const float*)d_in[20];
    const float* wpa  = (const float*)d_in[21];
    const float* bpa  = (const float*)d_in[22];
    float* out = (float*)d_out;

    k1a_conv<<<BB * 8, 256>>>(ctx, wcw, wca);
    k1b_setup<<<BB, 256>>>(dur, bcw, glnw, blnw, w1w, b1w,
                           bca, glna, blna, w1a, b1a);

    cudaFuncSetAttribute(k2_main, cudaFuncAttributeMaxDynamicSharedMemorySize,
                         K2_SMEM_BYTES);
    dim3 grid(TT / TTILE, BB);
    k2_main<<<grid, 256, K2_SMEM_BYTES>>>(
        ctx, mask, w1w, w2w, b2w, wpw, bpw,
        w1a, w2a, b2a, wpa, bpa, out);
}